// round 4
// baseline (speedup 1.0000x reference)
#include <cuda_runtime.h>

// Problem constants (fixed by dataset: D=256, H=W=384, N=65536)
#define GH 384
#define GW 384
#define DCH 256
#define D4 (DCH / 4)   // 64 float4 per token row

// Scratch: (r,c) -> token index or -1. 384*384*4 = 576 KB.
__device__ int g_map[GH * GW];

__global__ void init_map_kernel() {
    int i = blockIdx.x * blockDim.x + threadIdx.x;
    if (i < GH * GW) g_map[i] = -1;
}

__global__ void scatter_map_kernel(const int* __restrict__ coords, int N) {
    int n = blockIdx.x * blockDim.x + threadIdx.x;
    if (n < N) {
        int r = coords[2 * n];
        int c = coords[2 * n + 1];
        g_map[r * GW + c] = n;
    }
}

// Output layout is (D, N): out[ch*N + n]  (reference's conv[0,:,rows,cols] puts
// the advanced-index dim FIRST -> (N,D), then .T -> (D,N)).
//
// Each 64-thread group handles 8 consecutive tokens (2 batches of 4).
// Per batch: accumulate 4 tokens x 4 channels in registers, then register-
// transpose and store 4x STG.128 = out[ch*N + n..n+3] (coalesced over tokens).
// Block = 4 groups = 32 consecutive tokens -> every 32B output sector is
// completed within one thread (8 consecutive tokens per channel).
__global__ __launch_bounds__(256) void conv_gather_kernel(
    const float4* __restrict__ tokens,   // [N][64] float4
    const int*    __restrict__ coords,   // [N][2]
    const float*  __restrict__ weight,   // [256][9]
    const float4* __restrict__ bias4,    // [64] float4
    float*        __restrict__ out,      // [D][N]
    int N)
{
    const int d4  = threadIdx.x & 63;               // float4 index within channel dim
    const int grp = threadIdx.x >> 6;               // 0..3 within block

    // Per-thread weights for channels 4*d4 .. 4*d4+3, 9 taps each.
    float w[4][9];
#pragma unroll
    for (int j = 0; j < 4; j++) {
        const float* wrow = weight + (4 * d4 + j) * 9;
#pragma unroll
        for (int k = 0; k < 9; k++) w[j][k] = wrow[k];
    }
    const float4 b = bias4[d4];

    const int tok_stride = gridDim.x * 32;          // tokens per grid pass

    for (int n0 = blockIdx.x * 32; n0 < N; n0 += tok_stride) {
        const int gbase = n0 + grp * 8;             // this group's 8 tokens
#pragma unroll
        for (int half = 0; half < 2; half++) {
            const int nbase = gbase + half * 4;
            float4 res[4];
#pragma unroll
            for (int i = 0; i < 4; i++) {
                const int n = nbase + i;
                float4 acc = b;
                if (n < N) {
                    const int r = coords[2 * n];
                    const int c = coords[2 * n + 1];
#pragma unroll
                    for (int k = 0; k < 9; k++) {
                        const int rr = r + (k / 3) - 1;
                        const int cc = c + (k % 3) - 1;
                        if (rr < 0 || rr >= GH || cc < 0 || cc >= GW) continue;
                        const int nb = g_map[rr * GW + cc];   // broadcast load
                        if (nb < 0) continue;
                        const float4 t = tokens[nb * D4 + d4]; // coalesced row read
                        acc.x += w[0][k] * t.x;
                        acc.y += w[1][k] * t.y;
                        acc.z += w[2][k] * t.z;
                        acc.w += w[3][k] * t.w;
                    }
                }
                res[i] = acc;
            }
            // Transposed store: channel ch = 4*d4+j, tokens nbase..nbase+3.
            if (nbase + 3 < N) {
                float4* o0 = (float4*)(out + (size_t)(4 * d4 + 0) * N + nbase);
                float4* o1 = (float4*)(out + (size_t)(4 * d4 + 1) * N + nbase);
                float4* o2 = (float4*)(out + (size_t)(4 * d4 + 2) * N + nbase);
                float4* o3 = (float4*)(out + (size_t)(4 * d4 + 3) * N + nbase);
                *o0 = make_float4(res[0].x, res[1].x, res[2].x, res[3].x);
                *o1 = make_float4(res[0].y, res[1].y, res[2].y, res[3].y);
                *o2 = make_float4(res[0].z, res[1].z, res[2].z, res[3].z);
                *o3 = make_float4(res[0].w, res[1].w, res[2].w, res[3].w);
            } else {
                // Tail (unused for N % 32 == 0, kept for safety)
                for (int i = 0; i < 4; i++) {
                    const int n = nbase + i;
                    if (n >= N) break;
                    out[(size_t)(4 * d4 + 0) * N + n] = res[i].x;
                    out[(size_t)(4 * d4 + 1) * N + n] = res[i].y;
                    out[(size_t)(4 * d4 + 2) * N + n] = res[i].z;
                    out[(size_t)(4 * d4 + 3) * N + n] = res[i].w;
                }
            }
        }
    }
}

extern "C" void kernel_launch(void* const* d_in, const int* in_sizes, int n_in,
                              void* d_out, int out_size) {
    // Identify inputs by element count (order-proof):
    //   tokens: 16777216 f32 | coords: 131072 i32 | weight: 2304 f32
    //   bias: 256 f32 | grid_h/grid_w: 1 i32 each (ignored)
    const float* tokens = nullptr;
    const int*   coords = nullptr;
    const float* weight = nullptr;
    const float* bias   = nullptr;
    int N = 65536;

    for (int i = 0; i < n_in; i++) {
        const int sz = in_sizes[i];
        if (sz >= DCH * 1024) {                    // tokens (largest)
            tokens = (const float*)d_in[i];
            N = sz / DCH;
        } else if (sz == 2304) {
            weight = (const float*)d_in[i];
        } else if (sz == DCH) {
            bias = (const float*)d_in[i];
        } else if (sz > DCH && sz < DCH * 1024) {  // coords: 2*N
            coords = (const int*)d_in[i];
        }
    }

    float* out = (float*)d_out;

    init_map_kernel<<<(GH * GW + 255) / 256, 256>>>();
    scatter_map_kernel<<<(N + 255) / 256, 256>>>(coords, N);

    // 2048 blocks x 32 tokens = 65536 tokens in one pass.
    int nblk = (N + 31) / 32;
    conv_gather_kernel<<<nblk, 256>>>(
        (const float4*)tokens, coords, weight,
        (const float4*)bias, out, N);
}

// round 5
// speedup vs baseline: 1.4618x; 1.4618x over previous
#include <cuda_runtime.h>

// Problem constants (fixed by dataset: D=256, H=W=384, N=65536)
#define GH 384
#define GW 384
#define DCH 256
#define D4 (DCH / 4)   // 64 float4 per token row
#define NMAX 65536

// Scratch: (r,c) -> token index or -1. 384*384*4 = 576 KB.
__device__ int g_map[GH * GW];
// Per-token neighbor list: 9 tap slots (token idx or -1), padded to 12 ints (48B).
__device__ int g_nbr[NMAX * 12];

__global__ void init_map_kernel() {
    int i = blockIdx.x * blockDim.x + threadIdx.x;
    int4* m4 = (int4*)g_map;
    if (i < (GH * GW) / 4) m4[i] = make_int4(-1, -1, -1, -1);
}

__global__ void scatter_map_kernel(const int* __restrict__ coords, int N) {
    int n = blockIdx.x * blockDim.x + threadIdx.x;
    if (n < N) {
        int r = coords[2 * n];
        int c = coords[2 * n + 1];
        g_map[r * GW + c] = n;
    }
}

// One thread per token: resolve the coords->map chain once, store 9 slots.
__global__ void build_nbr_kernel(const int* __restrict__ coords, int N) {
    int n = blockIdx.x * blockDim.x + threadIdx.x;
    if (n >= N) return;
    const int r = coords[2 * n];
    const int c = coords[2 * n + 1];
    int nb[12];
#pragma unroll
    for (int k = 0; k < 9; k++) {
        const int rr = r + (k / 3) - 1;
        const int cc = c + (k % 3) - 1;
        const bool ok = ((unsigned)rr < GH) && ((unsigned)cc < GW);
        int idx = ok ? (rr * GW + cc) : 0;
        int v = g_map[idx];               // always load (clamped), select after
        nb[k] = ok ? v : -1;
    }
    nb[9] = nb[10] = nb[11] = -1;
    int4* dst = (int4*)(g_nbr + n * 12);
    dst[0] = make_int4(nb[0], nb[1], nb[2], nb[3]);
    dst[1] = make_int4(nb[4], nb[5], nb[6], nb[7]);
    dst[2] = make_int4(nb[8], nb[9], nb[10], nb[11]);
}

// Predicated gather: @p LDG.128 with zero-init destination — no branch (no
// BSSY/BSYNC), no memory traffic when the neighbor slot is empty.
__device__ __forceinline__ float4 ld_token_pred(const float4* __restrict__ base,
                                                int nb, int d4) {
    float4 t = make_float4(0.f, 0.f, 0.f, 0.f);
    const float4* p = base + (nb * D4 + d4);   // harmless arithmetic when nb<0
    asm("{ .reg .pred p; setp.ge.s32 p, %5, 0;\n\t"
        "@p ld.global.nc.v4.f32 {%0,%1,%2,%3}, [%4]; }"
        : "+f"(t.x), "+f"(t.y), "+f"(t.z), "+f"(t.w)
        : "l"(p), "r"(nb));
    return t;
}

// Output layout (D, N): out[ch*N + n].
// 64-thread group per token-batch: 4 channels/thread (float4), 8 tokens/group
// in two batches of 4; register transpose -> 4x STG.128 per batch at
// out[ch*N + n..n+3]. Block = 4 groups = 32 consecutive tokens.
__global__ __launch_bounds__(256) void conv_gather_kernel(
    const float4* __restrict__ tokens,   // [N][64] float4
    const float*  __restrict__ weight,   // [256][9]
    const float4* __restrict__ bias4,    // [64] float4
    float*        __restrict__ out,      // [D][N]
    int N)
{
    __shared__ int s_nbr[32 * 12];       // 32 tokens' neighbor lists

    const int d4  = threadIdx.x & 63;
    const int grp = threadIdx.x >> 6;
    const int n0  = blockIdx.x * 32;     // first token of this block

    // Stage this block's neighbor lists (coalesced), then broadcast-read.
    for (int i = threadIdx.x; i < 32 * 12; i += 256)
        s_nbr[i] = g_nbr[n0 * 12 + i];

    // Per-thread weights for channels 4*d4 .. 4*d4+3, 9 taps each.
    float w[4][9];
#pragma unroll
    for (int j = 0; j < 4; j++) {
        const float* wrow = weight + (4 * d4 + j) * 9;
#pragma unroll
        for (int k = 0; k < 9; k++) w[j][k] = wrow[k];
    }
    const float4 b = bias4[d4];

    __syncthreads();

#pragma unroll
    for (int half = 0; half < 2; half++) {
        const int tb = grp * 8 + half * 4;     // token offset within block
        float4 res[4];
#pragma unroll
        for (int i = 0; i < 4; i++) {
            const int* sl = s_nbr + (tb + i) * 12;   // broadcast reads
            float4 acc = b;
#pragma unroll
            for (int k = 0; k < 9; k++) {
                const int nb = sl[k];
                const float4 t = ld_token_pred(tokens, nb, d4);
                acc.x += w[0][k] * t.x;
                acc.y += w[1][k] * t.y;
                acc.z += w[2][k] * t.z;
                acc.w += w[3][k] * t.w;
            }
            res[i] = acc;
        }
        const int nbase = n0 + tb;
        float4* o0 = (float4*)(out + (size_t)(4 * d4 + 0) * N + nbase);
        float4* o1 = (float4*)(out + (size_t)(4 * d4 + 1) * N + nbase);
        float4* o2 = (float4*)(out + (size_t)(4 * d4 + 2) * N + nbase);
        float4* o3 = (float4*)(out + (size_t)(4 * d4 + 3) * N + nbase);
        *o0 = make_float4(res[0].x, res[1].x, res[2].x, res[3].x);
        *o1 = make_float4(res[0].y, res[1].y, res[2].y, res[3].y);
        *o2 = make_float4(res[0].z, res[1].z, res[2].z, res[3].z);
        *o3 = make_float4(res[0].w, res[1].w, res[2].w, res[3].w);
    }
}

extern "C" void kernel_launch(void* const* d_in, const int* in_sizes, int n_in,
                              void* d_out, int out_size) {
    // Identify inputs by element count (order-proof):
    //   tokens: 16777216 f32 | coords: 131072 i32 | weight: 2304 f32
    //   bias: 256 f32 | grid_h/grid_w: 1 i32 each (ignored)
    const float* tokens = nullptr;
    const int*   coords = nullptr;
    const float* weight = nullptr;
    const float* bias   = nullptr;
    int N = 65536;

    for (int i = 0; i < n_in; i++) {
        const int sz = in_sizes[i];
        if (sz >= DCH * 1024) {
            tokens = (const float*)d_in[i];
            N = sz / DCH;
        } else if (sz == 2304) {
            weight = (const float*)d_in[i];
        } else if (sz == DCH) {
            bias = (const float*)d_in[i];
        } else if (sz > DCH && sz < DCH * 1024) {
            coords = (const int*)d_in[i];
        }
    }

    float* out = (float*)d_out;

    init_map_kernel<<<(GH * GW / 4 + 255) / 256, 256>>>();
    scatter_map_kernel<<<(N + 255) / 256, 256>>>(coords, N);
    build_nbr_kernel<<<(N + 255) / 256, 256>>>(coords, N);

    conv_gather_kernel<<<(N + 31) / 32, 256>>>(
        (const float4*)tokens, weight, (const float4*)bias, out, N);
}

// round 6
// speedup vs baseline: 1.9519x; 1.3352x over previous
#include <cuda_runtime.h>

// Problem constants (fixed by dataset: D=256, H=W=384, N=65536)
#define GH 384
#define GW 384
#define DCH 256
#define D4 (DCH / 4)   // 64 float4 per token row
#define NMAX 65536

// Scratch: (r,c) -> token index or -1. 384*384*4 = 576 KB.
__device__ int g_map[GH * GW];
// Per-token neighbor list: 9 tap slots (token idx or -1), padded to 12 ints.
__device__ int g_nbr[NMAX * 12];

__global__ void init_map_kernel() {
    int i = blockIdx.x * blockDim.x + threadIdx.x;
    int4* m4 = (int4*)g_map;
    if (i < (GH * GW) / 4) m4[i] = make_int4(-1, -1, -1, -1);
}

__global__ void scatter_map_kernel(const int* __restrict__ coords, int N) {
    int n = blockIdx.x * blockDim.x + threadIdx.x;
    if (n < N) {
        int r = coords[2 * n];
        int c = coords[2 * n + 1];
        g_map[r * GW + c] = n;
    }
}

// One thread per token: resolve the coords->map chain once, store 9 slots.
__global__ void build_nbr_kernel(const int* __restrict__ coords, int N) {
    int n = blockIdx.x * blockDim.x + threadIdx.x;
    if (n >= N) return;
    const int r = coords[2 * n];
    const int c = coords[2 * n + 1];
    int nb[12];
#pragma unroll
    for (int k = 0; k < 9; k++) {
        const int rr = r + (k / 3) - 1;
        const int cc = c + (k % 3) - 1;
        const bool ok = ((unsigned)rr < GH) && ((unsigned)cc < GW);
        int idx = ok ? (rr * GW + cc) : 0;
        int v = g_map[idx];
        nb[k] = ok ? v : -1;
    }
    nb[9] = nb[10] = nb[11] = -1;
    int4* dst = (int4*)(g_nbr + n * 12);
    dst[0] = make_int4(nb[0], nb[1], nb[2], nb[3]);
    dst[1] = make_int4(nb[4], nb[5], nb[6], nb[7]);
    dst[2] = make_int4(nb[8], nb[9], nb[10], nb[11]);
}

// Predicated gather: @p LDG.128 with zero-init destination — no branch, no
// memory traffic when the neighbor slot is empty.
__device__ __forceinline__ float4 ld_token_pred(const float4* __restrict__ base,
                                                int nb, int d4) {
    float4 t = make_float4(0.f, 0.f, 0.f, 0.f);
    const float4* p = base + (nb * D4 + d4);
    asm("{ .reg .pred p; setp.ge.s32 p, %5, 0;\n\t"
        "@p ld.global.nc.v4.f32 {%0,%1,%2,%3}, [%4]; }"
        : "+f"(t.x), "+f"(t.y), "+f"(t.z), "+f"(t.w)
        : "l"(p), "r"(nb));
    return t;
}

// Output layout (D, N): out[ch*N + n].
// Compute phase: 64-thread group per 8 tokens (2 batches of 4), 4 channels per
// thread (float4); results staged to smem with XOR swizzle.
// Store phase: warp-contiguous 128B lines along n — full-sector stores.
//
// Swizzle: element ch of token tok lives at
//   s_out[tok*256 + 4*((ch>>2) ^ (tok>>2)) + (ch&3)]
// Write (fixed tok, lanes d4): permuted-contiguous 512B  -> conflict-free.
// Read  (fixed g, lanes (e,t4)): banks 4*((g^t4)&7)+e    -> conflict-free.
__global__ __launch_bounds__(256, 3) void conv_gather_kernel(
    const float4* __restrict__ tokens,   // [N][64] float4
    const float*  __restrict__ weight,   // [256][9]
    const float4* __restrict__ bias4,    // [64] float4
    float*        __restrict__ out,      // [D][N]
    int N)
{
    __shared__ int   s_nbr[32 * 12];     // 32 tokens' neighbor lists
    __shared__ float s_out[32 * 256];    // 32 tokens x 256 channels (swizzled)

    const int tid = threadIdx.x;
    const int d4  = tid & 63;
    const int grp = tid >> 6;
    const int n0  = blockIdx.x * 32;

    for (int i = tid; i < 32 * 12; i += 256)
        s_nbr[i] = g_nbr[n0 * 12 + i];

    // Per-thread weights for channels 4*d4 .. 4*d4+3, 9 taps each.
    float w[4][9];
#pragma unroll
    for (int j = 0; j < 4; j++) {
        const float* wrow = weight + (4 * d4 + j) * 9;
#pragma unroll
        for (int k = 0; k < 9; k++) w[j][k] = wrow[k];
    }
    const float4 b = bias4[d4];

    __syncthreads();

#pragma unroll
    for (int half = 0; half < 2; half++) {
        const int tb = grp * 8 + half * 4;          // token offset in block
        const int pg = d4 ^ (tb >> 2);              // swizzled float4 column
#pragma unroll
        for (int i = 0; i < 4; i++) {
            const int tok = tb + i;
            const int* sl = s_nbr + tok * 12;       // broadcast reads
            float4 acc = b;
#pragma unroll
            for (int k = 0; k < 9; k++) {
                const int nb = sl[k];
                const float4 t = ld_token_pred(tokens, nb, d4);
                acc.x += w[0][k] * t.x;
                acc.y += w[1][k] * t.y;
                acc.z += w[2][k] * t.z;
                acc.w += w[3][k] * t.w;
            }
            ((float4*)s_out)[tok * 64 + pg] = acc;  // conflict-free STS.128
        }
    }

    __syncthreads();

    // Store phase: 8 passes x (32 channels x 32 tokens). Each warp stores
    // 4 complete 128B lines (4 channels x 32 tokens x 4B).
    const int t4  = tid & 7;                        // token quad 0..7
    const int chb = tid >> 3;                       // 0..31
#pragma unroll
    for (int p = 0; p < 8; p++) {
        const int ch = p * 32 + chb;
        const int g  = ch >> 2;
        const int e  = ch & 3;
        const int pg = g ^ t4;                      // (4*t4+j)>>2 == t4
        float4 v;
        v.x = s_out[(4 * t4 + 0) * 256 + 4 * pg + e];
        v.y = s_out[(4 * t4 + 1) * 256 + 4 * pg + e];
        v.z = s_out[(4 * t4 + 2) * 256 + 4 * pg + e];
        v.w = s_out[(4 * t4 + 3) * 256 + 4 * pg + e];
        *(float4*)(out + (size_t)ch * N + n0 + 4 * t4) = v;
    }
}

extern "C" void kernel_launch(void* const* d_in, const int* in_sizes, int n_in,
                              void* d_out, int out_size) {
    // Identify inputs by element count (order-proof):
    //   tokens: 16777216 f32 | coords: 131072 i32 | weight: 2304 f32
    //   bias: 256 f32 | grid_h/grid_w: 1 i32 each (ignored)
    const float* tokens = nullptr;
    const int*   coords = nullptr;
    const float* weight = nullptr;
    const float* bias   = nullptr;
    int N = 65536;

    for (int i = 0; i < n_in; i++) {
        const int sz = in_sizes[i];
        if (sz >= DCH * 1024) {
            tokens = (const float*)d_in[i];
            N = sz / DCH;
        } else if (sz == 2304) {
            weight = (const float*)d_in[i];
        } else if (sz == DCH) {
            bias = (const float*)d_in[i];
        } else if (sz > DCH && sz < DCH * 1024) {
            coords = (const int*)d_in[i];
        }
    }

    float* out = (float*)d_out;

    init_map_kernel<<<(GH * GW / 4 + 255) / 256, 256>>>();
    scatter_map_kernel<<<(N + 255) / 256, 256>>>(coords, N);
    build_nbr_kernel<<<(N + 255) / 256, 256>>>(coords, N);

    conv_gather_kernel<<<(N + 31) / 32, 256>>>(
        (const float4*)tokens, weight, (const float4*)bias, out, N);
}